// round 16
// baseline (speedup 1.0000x reference)
#include <cuda_runtime.h>
#include <cstdint>

// ---------------- problem dims ----------------
#define BDIM 32
#define TDIM 4096
#define DDIM 512
#define MDIM (BDIM * TDIM)          // 131072

// ---------------- GEMM tiling ----------------
#define TILE_M 128
#define TILE_N 128
#define BK 32                        // k floats per chunk
#define NCHUNK (DDIM / BK)           // 16
#define STAGES 3
#define ROWF 36                      // padded row stride (144B = 9*16B -> conflict-free ldmatrix)
#define A_FLOATS (TILE_M * ROWF)     // 4608
#define B_FLOATS (TILE_N * ROWF)     // 4608
#define STAGE_FLOATS (A_FLOATS + B_FLOATS)       // 9216
#define SMEM_BYTES (STAGES * STAGE_FLOATS * 4)   // 110592

// ---------------- scratch ----------------
__device__ float g_w1[DDIM * DDIM];           // tf32-rounded W1
__device__ float g_w2[DDIM * DDIM];           // tf32-rounded W2
__device__ float g_u[(size_t)MDIM * DDIM];    // tanh(...), tf32-rounded
__device__ float g_zs[BDIM * DDIM];           // per-(b,d) sum of exp(s)
__device__ float g_as[BDIM * DDIM];           // per-(b,d) sum of h*exp(s)

// ---------------- helpers ----------------
__device__ __forceinline__ uint32_t smem_u32(const void* p) {
    uint32_t a;
    asm("{ .reg .u64 t; cvta.to.shared.u64 t, %1; cvt.u32.u64 %0, t; }" : "=r"(a) : "l"(p));
    return a;
}
__device__ __forceinline__ void cp16(uint32_t dst, const void* src) {
    asm volatile("cp.async.cg.shared.global [%0], [%1], 16;" :: "r"(dst), "l"(src));
}
__device__ __forceinline__ void ldsm4(uint32_t* r, uint32_t addr) {
    asm volatile("ldmatrix.sync.aligned.m8n8.x4.shared.b16 {%0,%1,%2,%3}, [%4];"
                 : "=r"(r[0]), "=r"(r[1]), "=r"(r[2]), "=r"(r[3]) : "r"(addr));
}
__device__ __forceinline__ float rna_tf32(float x) {
    float y;
    asm("cvt.rna.tf32.f32 %0, %1;" : "=f"(y) : "f"(x));
    return y;
}
__device__ __forceinline__ void mma8(float* c, const uint32_t* a, const uint32_t* b) {
    asm volatile(
        "mma.sync.aligned.m16n8k8.row.col.f32.tf32.tf32.f32 "
        "{%0,%1,%2,%3}, {%4,%5,%6,%7}, {%8,%9}, {%0,%1,%2,%3};"
        : "+f"(c[0]), "+f"(c[1]), "+f"(c[2]), "+f"(c[3])
        : "r"(a[0]), "r"(a[1]), "r"(a[2]), "r"(a[3]), "r"(b[0]), "r"(b[1]));
}
__device__ __forceinline__ void prefetch_l2(const void* p) {
    asm volatile("prefetch.global.L2 [%0];" :: "l"(p));
}
__device__ __forceinline__ float fast_tanh(float x) {
    float e = __expf(2.0f * x);
    return 1.0f - 2.0f / (e + 1.0f);
}

// ---------------- round W1/W2 to tf32 (RNA) + zero (Z,A) sums ----------------
__global__ void __launch_bounds__(256)
round_w_kernel(const float4* __restrict__ w1, float4* __restrict__ w1o,
               const float4* __restrict__ w2, float4* __restrict__ w2o) {
    // zero g_zs/g_as (16384 each) every replay: 64 blocks x 256 threads
    int z = blockIdx.x * 256 + threadIdx.x;
    g_zs[z] = 0.0f;
    g_as[z] = 0.0f;
    const float4* in  = (blockIdx.x < 32) ? w1  : w2;
    float4*       outp = (blockIdx.x < 32) ? w1o : w2o;
    size_t i = (size_t)(blockIdx.x & 31) * 2048 + threadIdx.x;
#pragma unroll
    for (int k = 0; k < 8; k++) {
        float4 v = in[i + (size_t)k * 256];
        v.x = rna_tf32(v.x); v.y = rna_tf32(v.y);
        v.z = rna_tf32(v.z); v.w = rna_tf32(v.w);
        outp[i + (size_t)k * 256] = v;
    }
}

// ---------------- half-stage loaders: 4 cp16 each ----------------
__device__ __forceinline__ void load_half(const float* __restrict__ S,
                                          int r0, int kc,
                                          uint32_t st, int tid) {
#pragma unroll
    for (int it = 0; it < 4; it++) {             // 1024 x 16B
        int idx = tid + it * 256;
        int r = idx >> 3, c = idx & 7;
        cp16(st + r * 144 + c * 16, S + (size_t)(r0 + r) * DDIM + kc * BK + c * 4);
    }
}

// ---------------- shared mainloop: 8 warps, 64x32 warp tile ----------------
struct FragCtx {
    uint32_t s_base, a_off, b_off;
    int m0, n0, wm, wn, kph;
};

__device__ __forceinline__ FragCtx make_ctx(uint32_t s_base, int tid, int yblk) {
    const int lane = tid & 31;
    const int wid = tid >> 5;
    FragCtx fc;
    fc.s_base = s_base;
    fc.m0 = yblk * TILE_M;
    fc.n0 = blockIdx.x * TILE_N;
    fc.wm = (wid >> 2) * 64;                     // 2 warps along M
    fc.wn = (wid & 3) * 32;                      // 4 warps along N
    fc.kph = (wid >> 2) * 2;                     // kstep phase: SMSP-mates de-phased by 2
    fc.a_off = (uint32_t)(fc.wm + ((lane >> 3) & 1) * 8 + (lane & 7)) * 144
               + (uint32_t)(lane >> 4) * 16;
    fc.b_off = (uint32_t)(fc.wn + (lane >> 4) * 8 + (lane & 7)) * 144
               + (uint32_t)((lane >> 3) & 1) * 16;
    return fc;
}

// load all fragments for one k8-step (raw: mma HW truncates fp32->tf32)
__device__ __forceinline__ void ld_frags(uint32_t stA, uint32_t stB,
                                         const FragCtx& fc, int kk,
                                         uint32_t ar[4][4], uint32_t br[2][4]) {
#pragma unroll
    for (int g = 0; g < 2; g++)
        ldsm4(br[g], stB + fc.b_off + g * 16 * 144 + kk * 32);
#pragma unroll
    for (int f = 0; f < 4; f++)
        ldsm4(ar[f], stA + fc.a_off + f * 16 * 144 + kk * 32);
}

__device__ __forceinline__ void mma_step(float acc[4][4][4],
                                         uint32_t ar[4][4], uint32_t br[2][4]) {
#pragma unroll
    for (int fm = 0; fm < 4; fm++) {
#pragma unroll
        for (int fn = 0; fn < 4; fn++) {
            const uint32_t b2[2] = { br[fn >> 1][(fn & 1) * 2],
                                     br[fn >> 1][(fn & 1) * 2 + 1] };
            mma8(acc[fm][fn], ar[fm], b2);
        }
    }
}

// PF: L2-prefetch pfbase tile (128 rows x 512B) during the last chunk.
template <bool PF>
__device__ __forceinline__ void gemm_mainloop(const float* __restrict__ A,
                                              const float* __restrict__ W,
                                              const FragCtx& fc, int tid,
                                              const float* __restrict__ pfbase,
                                              float acc[4][4][4]) {
#pragma unroll
    for (int s = 0; s < STAGES - 1; s++) {
        load_half(A, fc.m0, s, fc.s_base + s * STAGE_FLOATS * 4, tid);
        load_half(W, fc.n0, s, fc.s_base + s * STAGE_FLOATS * 4 + A_FLOATS * 4, tid);
        asm volatile("cp.async.commit_group;" ::: "memory");
    }

    uint32_t ar[4][4];                           // single-buffered fragments (reg-neutral)
    uint32_t br[2][4];

    int st_c = 0;                                // consume stage, no modulo
    int st_p = STAGES - 1;                       // produce stage

    for (int i = 0; i < NCHUNK; i++) {
        asm volatile("cp.async.wait_group %0;" :: "n"(STAGES - 2));
        __syncthreads();

        const uint32_t stA = fc.s_base + st_c * STAGE_FLOATS * 4;
        const uint32_t stB = stA + A_FLOATS * 4;

        // first kstep (per-warp phase) FIRST: tensor work starts before any cp.async
        ld_frags(stA, stB, fc, fc.kph, ar, br);

        const int j = i + STAGES - 1;
        const uint32_t stP = fc.s_base + st_p * STAGE_FLOATS * 4;

        // A-half of next chunk's loads
        if (j < NCHUNK) load_half(A, fc.m0, j, stP, tid);

        if (PF && i == NCHUNK - 1) {
            // warm L2 for the epilogue's h tile: 512 lines of 128B, 2 per thread
#pragma unroll
            for (int k = 0; k < 2; k++) {
                int L = tid * 2 + k;
                prefetch_l2(pfbase + (size_t)(L >> 2) * DDIM + (L & 3) * 32);
            }
        }

        mma_step(acc, ar, br);                   // phase kstep

        // B-half issued under first kstep's MMA shadow; one commit covers both halves
        if (j < NCHUNK) load_half(W, fc.n0, j, stP + A_FLOATS * 4, tid);
        asm volatile("cp.async.commit_group;" ::: "memory");

#pragma unroll
        for (int kk = 1; kk < BK / 8; kk++) {    // remaining ksteps, rotated per warp
            const int k2 = (kk + fc.kph) & 3;
            ld_frags(stA, stB, fc, k2, ar, br);
            mma_step(acc, ar, br);
        }

        st_c = (st_c == STAGES - 1) ? 0 : st_c + 1;
        st_p = (st_p == STAGES - 1) ? 0 : st_p + 1;
    }
    asm volatile("cp.async.wait_group 0;" ::: "memory");
}

// ---------------- GEMM1: u = rna_tf32(tanh(h@W1^T + b1)), raw-h input ----------------
__global__ void __launch_bounds__(256, 2)
gemm1_kernel(const float* __restrict__ A, const float* __restrict__ W,
             const float* __restrict__ bias, float* __restrict__ C) {
    extern __shared__ float sm[];
    const int tid = threadIdx.x;
    const int lane = tid & 31;

    float acc[4][4][4];
#pragma unroll
    for (int i = 0; i < 4; i++)
#pragma unroll
        for (int j = 0; j < 4; j++)
#pragma unroll
            for (int k = 0; k < 4; k++) acc[i][j][k] = 0.0f;

    FragCtx fc = make_ctx(smem_u32(sm), tid, blockIdx.y);
    gemm_mainloop<false>(A, W, fc, tid, nullptr, acc);

    const int g = lane >> 2;
    const int tg = lane & 3;
#pragma unroll
    for (int fm = 0; fm < 4; fm++) {
        const int row = fc.m0 + fc.wm + fm * 16 + g;
#pragma unroll
        for (int fn = 0; fn < 4; fn++) {
            const int col = fc.n0 + fc.wn + fn * 8 + tg * 2;
            const float2 bb = *(const float2*)(bias + col);
            float v0 = rna_tf32(fast_tanh(acc[fm][fn][0] + bb.x));
            float v1 = rna_tf32(fast_tanh(acc[fm][fn][1] + bb.y));
            float v2 = rna_tf32(fast_tanh(acc[fm][fn][2] + bb.x));
            float v3 = rna_tf32(fast_tanh(acc[fm][fn][3] + bb.y));
            *(float2*)(C + (size_t)row * DDIM + col) = make_float2(v0, v1);
            *(float2*)(C + (size_t)(row + 8) * DDIM + col) = make_float2(v2, v3);
        }
    }
}

// ---------------- GEMM2 fused: s = u@W2^T, then no-max softmax partial sums ----------
// Logits |s| <~ 4 (u in (-1,1), W2 ~ N(0,1/512)): exp(s) is overflow-safe without
// max subtraction -> accumulate Z=sum(exp), A=sum(h*exp) straight into atomics.
// y mapping REVERSED: first waves read the u rows gemm1 wrote last (L2-hot).
__global__ void __launch_bounds__(256, 2)
gemm2_fused_kernel(const float* __restrict__ A, const float* __restrict__ W,
                   const float* __restrict__ h) {
    extern __shared__ float sm[];
    const int tid = threadIdx.x;
    const int lane = tid & 31;
    const int yblk = gridDim.y - 1 - blockIdx.y;  // reverse-y for L2 reuse of u

    float acc[4][4][4];
#pragma unroll
    for (int i = 0; i < 4; i++)
#pragma unroll
        for (int j = 0; j < 4; j++)
#pragma unroll
            for (int k = 0; k < 4; k++) acc[i][j][k] = 0.0f;

    FragCtx fc = make_ctx(smem_u32(sm), tid, yblk);
    const float* hp0 = h + (size_t)fc.m0 * DDIM + fc.n0;
    gemm_mainloop<true>(A, W, fc, tid, hp0, acc);
    __syncthreads();                              // pipeline smem now reusable

    // ---- dump s tile to smem: [row][col], stride 132 floats ----
    const int g = lane >> 2;
    const int tg = lane & 3;
#pragma unroll
    for (int fm = 0; fm < 4; fm++) {
        const int row = fc.wm + fm * 16 + g;
#pragma unroll
        for (int fn = 0; fn < 4; fn++) {
            const int col = fc.wn + fn * 8 + tg * 2;
            *(float2*)(sm + row * 132 + col) =
                make_float2(acc[fm][fn][0], acc[fm][fn][1]);
            *(float2*)(sm + (row + 8) * 132 + col) =
                make_float2(acc[fm][fn][2], acc[fm][fn][3]);
        }
    }
    __syncthreads();

    // ---- per-column exp-sum over 64 rows + weighted h (2 halves, dual acc) ----
    const int col = tid & 127;
    const int half = tid >> 7;
    const float* hp = hp0 + (size_t)(half * 64) * DDIM + col;

    float Z0 = 0.0f, Z1 = 0.0f, a0 = 0.0f, a1 = 0.0f;
#pragma unroll 4
    for (int r = 0; r < 64; r += 2) {
        float p0 = __expf(sm[(half * 64 + r) * 132 + col]);
        float p1 = __expf(sm[(half * 64 + r + 1) * 132 + col]);
        float h0 = hp[(size_t)r * DDIM];
        float h1 = hp[(size_t)(r + 1) * DDIM];
        Z0 += p0; Z1 += p1;
        a0 += h0 * p0; a1 += h1 * p1;
    }

    const int b = yblk >> 5;
    const int d = b * DDIM + fc.n0 + col;
    atomicAdd(&g_zs[d], Z0 + Z1);
    atomicAdd(&g_as[d], a0 + a1);
}

// ---------------- finalize: out[d] = sum_b A[b,d] / Z[b,d] ----------------
__global__ void __launch_bounds__(256)
finalize_kernel(float* __restrict__ out) {
    const int d = blockIdx.x * 256 + threadIdx.x;
    float total = 0.0f;
#pragma unroll
    for (int b = 0; b < BDIM; b++)
        total += g_as[b * DDIM + d] / g_zs[b * DDIM + d];
    out[d] = total;
}

// ---------------- host launcher ----------------
extern "C" void kernel_launch(void* const* d_in, const int* in_sizes, int n_in,
                              void* d_out, int out_size) {
    const float* h  = (const float*)d_in[0];
    const float* W1 = (const float*)d_in[1];
    const float* b1 = (const float*)d_in[2];
    const float* W2 = (const float*)d_in[3];
    float* out = (float*)d_out;

    float *w1r, *w2r, *u_ptr;
    cudaGetSymbolAddress((void**)&w1r,   g_w1);
    cudaGetSymbolAddress((void**)&w2r,   g_w2);
    cudaGetSymbolAddress((void**)&u_ptr, g_u);

    cudaFuncSetAttribute(gemm1_kernel,       cudaFuncAttributeMaxDynamicSharedMemorySize, SMEM_BYTES);
    cudaFuncSetAttribute(gemm2_fused_kernel, cudaFuncAttributeMaxDynamicSharedMemorySize, SMEM_BYTES);

    // round W1+W2 to tf32 (RNA) + zero (Z,A) sums (each replay)
    round_w_kernel<<<64, 256>>>((const float4*)W1, (float4*)w1r,
                                (const float4*)W2, (float4*)w2r);

    dim3 ggrid(DDIM / TILE_N, MDIM / TILE_M);    // (4, 1024)

    gemm1_kernel<<<ggrid, 256, SMEM_BYTES>>>(h, w1r, b1, u_ptr);
    gemm2_fused_kernel<<<ggrid, 256, SMEM_BYTES>>>(u_ptr, w2r, h);

    finalize_kernel<<<DDIM / 256, 256>>>(out);
}

// round 17
// speedup vs baseline: 1.0143x; 1.0143x over previous
#include <cuda_runtime.h>
#include <cstdint>

// ---------------- problem dims ----------------
#define BDIM 32
#define TDIM 4096
#define DDIM 512
#define MDIM (BDIM * TDIM)          // 131072

// ---------------- GEMM tiling ----------------
#define TILE_M 128
#define TILE_N 128
#define BK 32                        // k floats per chunk
#define NCHUNK (DDIM / BK)           // 16
#define STAGES 3
#define ROWF 36                      // padded row stride (144B = 9*16B -> conflict-free ldmatrix)
#define A_FLOATS (TILE_M * ROWF)     // 4608
#define B_FLOATS (TILE_N * ROWF)     // 4608
#define STAGE_FLOATS (A_FLOATS + B_FLOATS)       // 9216
#define SMEM_BYTES (STAGES * STAGE_FLOATS * 4)   // 110592

// ---------------- scratch ----------------
__device__ float g_w1[DDIM * DDIM];           // tf32-rounded W1
__device__ float g_w2[DDIM * DDIM];           // tf32-rounded W2
__device__ float g_u[(size_t)MDIM * DDIM];    // tanh(...), tf32-rounded
__device__ float g_zs[BDIM * DDIM];           // per-(b,d) sum of exp(s)
__device__ float g_as[BDIM * DDIM];           // per-(b,d) sum of h*exp(s)

// ---------------- helpers ----------------
__device__ __forceinline__ uint32_t smem_u32(const void* p) {
    uint32_t a;
    asm("{ .reg .u64 t; cvta.to.shared.u64 t, %1; cvt.u32.u64 %0, t; }" : "=r"(a) : "l"(p));
    return a;
}
__device__ __forceinline__ void cp16(uint32_t dst, const void* src) {
    asm volatile("cp.async.cg.shared.global [%0], [%1], 16;" :: "r"(dst), "l"(src));
}
__device__ __forceinline__ void ldsm4(uint32_t* r, uint32_t addr) {
    asm volatile("ldmatrix.sync.aligned.m8n8.x4.shared.b16 {%0,%1,%2,%3}, [%4];"
                 : "=r"(r[0]), "=r"(r[1]), "=r"(r[2]), "=r"(r[3]) : "r"(addr));
}
__device__ __forceinline__ float rna_tf32(float x) {
    float y;
    asm("cvt.rna.tf32.f32 %0, %1;" : "=f"(y) : "f"(x));
    return y;
}
__device__ __forceinline__ void mma8(float* c, const uint32_t* a, const uint32_t* b) {
    asm volatile(
        "mma.sync.aligned.m16n8k8.row.col.f32.tf32.tf32.f32 "
        "{%0,%1,%2,%3}, {%4,%5,%6,%7}, {%8,%9}, {%0,%1,%2,%3};"
        : "+f"(c[0]), "+f"(c[1]), "+f"(c[2]), "+f"(c[3])
        : "r"(a[0]), "r"(a[1]), "r"(a[2]), "r"(a[3]), "r"(b[0]), "r"(b[1]));
}
__device__ __forceinline__ void prefetch_l2(const void* p) {
    asm volatile("prefetch.global.L2 [%0];" :: "l"(p));
}
__device__ __forceinline__ float fast_tanh(float x) {
    float e = __expf(2.0f * x);
    return 1.0f - 2.0f / (e + 1.0f);
}

// ---------------- round W1/W2 to tf32 (RNA) + zero (Z,A) sums + zero out ----------------
__global__ void __launch_bounds__(256)
round_w_kernel(const float4* __restrict__ w1, float4* __restrict__ w1o,
               const float4* __restrict__ w2, float4* __restrict__ w2o,
               float* __restrict__ out) {
    // zero g_zs/g_as (16384 each) + out[512] every replay: 64 blocks x 256 threads
    int z = blockIdx.x * 256 + threadIdx.x;
    g_zs[z] = 0.0f;
    g_as[z] = 0.0f;
    if (blockIdx.x < 2)
        out[blockIdx.x * 256 + threadIdx.x] = 0.0f;
    const float4* in  = (blockIdx.x < 32) ? w1  : w2;
    float4*       outp = (blockIdx.x < 32) ? w1o : w2o;
    size_t i = (size_t)(blockIdx.x & 31) * 2048 + threadIdx.x;
#pragma unroll
    for (int k = 0; k < 8; k++) {
        float4 v = in[i + (size_t)k * 256];
        v.x = rna_tf32(v.x); v.y = rna_tf32(v.y);
        v.z = rna_tf32(v.z); v.w = rna_tf32(v.w);
        outp[i + (size_t)k * 256] = v;
    }
}

// ---------------- half-stage loaders: 4 cp16 each ----------------
__device__ __forceinline__ void load_half(const float* __restrict__ S,
                                          int r0, int kc,
                                          uint32_t st, int tid) {
#pragma unroll
    for (int it = 0; it < 4; it++) {             // 1024 x 16B
        int idx = tid + it * 256;
        int r = idx >> 3, c = idx & 7;
        cp16(st + r * 144 + c * 16, S + (size_t)(r0 + r) * DDIM + kc * BK + c * 4);
    }
}

// ---------------- shared mainloop: 8 warps, 64x32 warp tile ----------------
struct FragCtx {
    uint32_t s_base, a_off, b_off;
    int m0, n0, wm, wn, kph;
};

__device__ __forceinline__ FragCtx make_ctx(uint32_t s_base, int tid, int yblk) {
    const int lane = tid & 31;
    const int wid = tid >> 5;
    FragCtx fc;
    fc.s_base = s_base;
    fc.m0 = yblk * TILE_M;
    fc.n0 = blockIdx.x * TILE_N;
    fc.wm = (wid >> 2) * 64;                     // 2 warps along M
    fc.wn = (wid & 3) * 32;                      // 4 warps along N
    fc.kph = (wid >> 2) * 2;                     // kstep phase: SMSP-mates de-phased by 2
    fc.a_off = (uint32_t)(fc.wm + ((lane >> 3) & 1) * 8 + (lane & 7)) * 144
               + (uint32_t)(lane >> 4) * 16;
    fc.b_off = (uint32_t)(fc.wn + (lane >> 4) * 8 + (lane & 7)) * 144
               + (uint32_t)((lane >> 3) & 1) * 16;
    return fc;
}

// load all fragments for one k8-step (raw: mma HW truncates fp32->tf32)
__device__ __forceinline__ void ld_frags(uint32_t stA, uint32_t stB,
                                         const FragCtx& fc, int kk,
                                         uint32_t ar[4][4], uint32_t br[2][4]) {
#pragma unroll
    for (int g = 0; g < 2; g++)
        ldsm4(br[g], stB + fc.b_off + g * 16 * 144 + kk * 32);
#pragma unroll
    for (int f = 0; f < 4; f++)
        ldsm4(ar[f], stA + fc.a_off + f * 16 * 144 + kk * 32);
}

__device__ __forceinline__ void mma_step(float acc[4][4][4],
                                         uint32_t ar[4][4], uint32_t br[2][4]) {
#pragma unroll
    for (int fm = 0; fm < 4; fm++) {
#pragma unroll
        for (int fn = 0; fn < 4; fn++) {
            const uint32_t b2[2] = { br[fn >> 1][(fn & 1) * 2],
                                     br[fn >> 1][(fn & 1) * 2 + 1] };
            mma8(acc[fm][fn], ar[fm], b2);
        }
    }
}

// PF: L2-prefetch pfbase tile (128 rows x 512B) during the last chunk.
template <bool PF>
__device__ __forceinline__ void gemm_mainloop(const float* __restrict__ A,
                                              const float* __restrict__ W,
                                              const FragCtx& fc, int tid,
                                              const float* __restrict__ pfbase,
                                              float acc[4][4][4]) {
#pragma unroll
    for (int s = 0; s < STAGES - 1; s++) {
        load_half(A, fc.m0, s, fc.s_base + s * STAGE_FLOATS * 4, tid);
        load_half(W, fc.n0, s, fc.s_base + s * STAGE_FLOATS * 4 + A_FLOATS * 4, tid);
        asm volatile("cp.async.commit_group;" ::: "memory");
    }

    uint32_t ar[4][4];                           // single-buffered fragments (reg-neutral)
    uint32_t br[2][4];

    int st_c = 0;                                // consume stage, no modulo
    int st_p = STAGES - 1;                       // produce stage

    for (int i = 0; i < NCHUNK; i++) {
        asm volatile("cp.async.wait_group %0;" :: "n"(STAGES - 2));
        __syncthreads();

        const uint32_t stA = fc.s_base + st_c * STAGE_FLOATS * 4;
        const uint32_t stB = stA + A_FLOATS * 4;

        // first kstep (per-warp phase) FIRST: tensor work starts before any cp.async
        ld_frags(stA, stB, fc, fc.kph, ar, br);

        const int j = i + STAGES - 1;
        const uint32_t stP = fc.s_base + st_p * STAGE_FLOATS * 4;

        // A-half of next chunk's loads
        if (j < NCHUNK) load_half(A, fc.m0, j, stP, tid);

        if (PF && i == NCHUNK - 1) {
            // warm L2 for the epilogue's h tile: 512 lines of 128B, 2 per thread
#pragma unroll
            for (int k = 0; k < 2; k++) {
                int L = tid * 2 + k;
                prefetch_l2(pfbase + (size_t)(L >> 2) * DDIM + (L & 3) * 32);
            }
        }

        mma_step(acc, ar, br);                   // phase kstep

        // B-half issued under first kstep's MMA shadow; one commit covers both halves
        if (j < NCHUNK) load_half(W, fc.n0, j, stP + A_FLOATS * 4, tid);
        asm volatile("cp.async.commit_group;" ::: "memory");

#pragma unroll
        for (int kk = 1; kk < BK / 8; kk++) {    // remaining ksteps, rotated per warp
            const int k2 = (kk + fc.kph) & 3;
            ld_frags(stA, stB, fc, k2, ar, br);
            mma_step(acc, ar, br);
        }

        st_c = (st_c == STAGES - 1) ? 0 : st_c + 1;
        st_p = (st_p == STAGES - 1) ? 0 : st_p + 1;
    }
    asm volatile("cp.async.wait_group 0;" ::: "memory");
}

// ---------------- GEMM1: u = rna_tf32(tanh(h@W1^T + b1)), raw-h input ----------------
__global__ void __launch_bounds__(256, 2)
gemm1_kernel(const float* __restrict__ A, const float* __restrict__ W,
             const float* __restrict__ bias, float* __restrict__ C) {
    extern __shared__ float sm[];
    const int tid = threadIdx.x;
    const int lane = tid & 31;

    float acc[4][4][4];
#pragma unroll
    for (int i = 0; i < 4; i++)
#pragma unroll
        for (int j = 0; j < 4; j++)
#pragma unroll
            for (int k = 0; k < 4; k++) acc[i][j][k] = 0.0f;

    FragCtx fc = make_ctx(smem_u32(sm), tid, blockIdx.y);
    gemm_mainloop<false>(A, W, fc, tid, nullptr, acc);

    const int g = lane >> 2;
    const int tg = lane & 3;
#pragma unroll
    for (int fm = 0; fm < 4; fm++) {
        const int row = fc.m0 + fc.wm + fm * 16 + g;
#pragma unroll
        for (int fn = 0; fn < 4; fn++) {
            const int col = fc.n0 + fc.wn + fn * 8 + tg * 2;
            const float2 bb = *(const float2*)(bias + col);
            float v0 = rna_tf32(fast_tanh(acc[fm][fn][0] + bb.x));
            float v1 = rna_tf32(fast_tanh(acc[fm][fn][1] + bb.y));
            float v2 = rna_tf32(fast_tanh(acc[fm][fn][2] + bb.x));
            float v3 = rna_tf32(fast_tanh(acc[fm][fn][3] + bb.y));
            *(float2*)(C + (size_t)row * DDIM + col) = make_float2(v0, v1);
            *(float2*)(C + (size_t)(row + 8) * DDIM + col) = make_float2(v2, v3);
        }
    }
}

// ---------------- GEMM2 fused: s = u@W2^T, then no-max softmax partial sums ----------
// Logits |s| <~ 4 (u in (-1,1), W2 ~ N(0,1/512)): exp(s) is overflow-safe without
// max subtraction -> accumulate Z=sum(exp), A=sum(h*exp) straight into atomics.
// y mapping REVERSED: first waves read the u rows gemm1 wrote last (L2-hot).
__global__ void __launch_bounds__(256, 2)
gemm2_fused_kernel(const float* __restrict__ A, const float* __restrict__ W,
                   const float* __restrict__ h) {
    extern __shared__ float sm[];
    const int tid = threadIdx.x;
    const int lane = tid & 31;
    const int yblk = gridDim.y - 1 - blockIdx.y;  // reverse-y for L2 reuse of u

    float acc[4][4][4];
#pragma unroll
    for (int i = 0; i < 4; i++)
#pragma unroll
        for (int j = 0; j < 4; j++)
#pragma unroll
            for (int k = 0; k < 4; k++) acc[i][j][k] = 0.0f;

    FragCtx fc = make_ctx(smem_u32(sm), tid, yblk);
    const float* hp0 = h + (size_t)fc.m0 * DDIM + fc.n0;
    gemm_mainloop<true>(A, W, fc, tid, hp0, acc);
    __syncthreads();                              // pipeline smem now reusable

    // ---- dump s tile to smem: [row][col], stride 132 floats ----
    const int g = lane >> 2;
    const int tg = lane & 3;
#pragma unroll
    for (int fm = 0; fm < 4; fm++) {
        const int row = fc.wm + fm * 16 + g;
#pragma unroll
        for (int fn = 0; fn < 4; fn++) {
            const int col = fc.wn + fn * 8 + tg * 2;
            *(float2*)(sm + row * 132 + col) =
                make_float2(acc[fm][fn][0], acc[fm][fn][1]);
            *(float2*)(sm + (row + 8) * 132 + col) =
                make_float2(acc[fm][fn][2], acc[fm][fn][3]);
        }
    }
    __syncthreads();

    // ---- per-column exp-sum over 64 rows + weighted h (2 halves, dual acc) ----
    const int col = tid & 127;
    const int half = tid >> 7;
    const float* hp = hp0 + (size_t)(half * 64) * DDIM + col;

    float Z0 = 0.0f, Z1 = 0.0f, a0 = 0.0f, a1 = 0.0f;
#pragma unroll 4
    for (int r = 0; r < 64; r += 2) {
        float p0 = __expf(sm[(half * 64 + r) * 132 + col]);
        float p1 = __expf(sm[(half * 64 + r + 1) * 132 + col]);
        float h0 = hp[(size_t)r * DDIM];
        float h1 = hp[(size_t)(r + 1) * DDIM];
        Z0 += p0; Z1 += p1;
        a0 += h0 * p0; a1 += h1 * p1;
    }

    const int b = yblk >> 5;
    const int d = b * DDIM + fc.n0 + col;
    atomicAdd(&g_zs[d], Z0 + Z1);
    atomicAdd(&g_as[d], a0 + a1);
}

// ---------------- finalize: out[d] += A[b,d]/Z[b,d], parallel over (b, d) ----------------
__global__ void __launch_bounds__(256)
finalize_kernel(float* __restrict__ out) {
    const int d = (blockIdx.x & 1) * 256 + threadIdx.x;
    const int b = blockIdx.x >> 1;
    const int idx = b * DDIM + d;
    atomicAdd(&out[d], g_as[idx] / g_zs[idx]);
}

// ---------------- host launcher ----------------
extern "C" void kernel_launch(void* const* d_in, const int* in_sizes, int n_in,
                              void* d_out, int out_size) {
    const float* h  = (const float*)d_in[0];
    const float* W1 = (const float*)d_in[1];
    const float* b1 = (const float*)d_in[2];
    const float* W2 = (const float*)d_in[3];
    float* out = (float*)d_out;

    float *w1r, *w2r, *u_ptr;
    cudaGetSymbolAddress((void**)&w1r,   g_w1);
    cudaGetSymbolAddress((void**)&w2r,   g_w2);
    cudaGetSymbolAddress((void**)&u_ptr, g_u);

    cudaFuncSetAttribute(gemm1_kernel,       cudaFuncAttributeMaxDynamicSharedMemorySize, SMEM_BYTES);
    cudaFuncSetAttribute(gemm2_fused_kernel, cudaFuncAttributeMaxDynamicSharedMemorySize, SMEM_BYTES);

    // round W1+W2 to tf32 (RNA) + zero (Z,A) sums + zero out[512] (each replay)
    round_w_kernel<<<64, 256>>>((const float4*)W1, (float4*)w1r,
                                (const float4*)W2, (float4*)w2r, out);

    dim3 ggrid(DDIM / TILE_N, MDIM / TILE_M);    // (4, 1024)

    gemm1_kernel<<<ggrid, 256, SMEM_BYTES>>>(h, w1r, b1, u_ptr);
    gemm2_fused_kernel<<<ggrid, 256, SMEM_BYTES>>>(u_ptr, w2r, h);

    // 64 blocks = 32 batches x 2 d-halves; one ratio + atomic add per thread
    finalize_kernel<<<BDIM * 2, 256>>>(out);
}